// round 7
// baseline (speedup 1.0000x reference)
#include <cuda_runtime.h>
#include <stdint.h>

// ============================================================================
// One-sweep speculative radix-select threshold kernel (v7).
//
// thresh = rank-mf (0-based) entry of the descending sort of all inputs.
// out[i] = x[i] < thresh ? 0 : x[i].
//
// Key map (order-preserving): key = u ^ (sign ? 0xFFFFFFFF : 0x80000000).
//
// TWO launches, no init kernel (all globals self-cleaning across graph
// replays; device statics are zero at module load):
//   pass1:   read all, write out thresholded at 1.75, compact candidate
//            key/idx into per-warp slices, smem 4096-bin hist of key>>20.
//            Last block decides mode + selects digit 1 (12 bits).
//   resolve: persistent kernel with device grid-sync.
//            phase A: scan slices; zero out[] below 12-bit prefix; compact
//                     prefix-matched (k,idx) into dense cbuf; hist bits[19:8].
//            phase B: scan cbuf; zero below 24-bit prefix; hist bits[7:0].
//            phase C: zero cbuf entries with 24-bit prefix match and k < kf.
//            Fallback (mode 1): 3 full-read hist phases + full rewrite.
//            Trivial (mode 2): thresh=0 rewrite.
// ============================================================================

#define NB     1024
#define NT     256
#define NWARP  (NB * NT / 32)     // 8192
#define SLICE  512u
#define CBUF_CAP (NWARP * SLICE)  // 4M entries
#define FKEY   0xBFE00000u        // key(+1.75f)
#define HBINS  4096
#define RGRID  512                // <= resident capacity (regs/smem checked)

__device__ unsigned g_h[HBINS];
__device__ unsigned g_key[NWARP * SLICE];   // 16 MB
__device__ unsigned g_idx[NWARP * SLICE];   // 16 MB
__device__ unsigned g_ck[CBUF_CAP];         // 16 MB dense candidate keys
__device__ unsigned g_ci[CBUF_CAP];         // 16 MB dense candidate idx
__device__ unsigned g_warpcnt[NWARP];
__device__ unsigned g_ctr[8];
__device__ unsigned g_go[8];
__device__ unsigned g_cand_cnt;
__device__ unsigned g_nscratch;
__device__ int      g_mode;       // 0=spec, 1=fallback, 2=trivial
__device__ int      g_overflow;
__device__ unsigned g_pref;       // accumulated digit prefix (right-aligned)
__device__ unsigned g_rank;       // residual rank
__device__ unsigned g_key32;      // final exact key
__device__ float    g_thresh;

__device__ __forceinline__ unsigned fmap_u(unsigned u) {
    return u ^ ((unsigned)((int)u >> 31) | 0x80000000u);
}
__device__ __forceinline__ float finv_map(unsigned k) {
    unsigned u = (k & 0x80000000u) ? (k ^ 0x80000000u) : ~k;
    return __uint_as_float(u);
}

// Block-cooperative descending rank-select over g_h[0..nbins). 256 threads.
// Appends digit to g_pref, updates g_rank, zeroes g_h[0..nbins).
__device__ void select_digitN(int nbins, int append_bits, int final_stage) {
    __shared__ unsigned tsum[256];
    __shared__ unsigned wsum[8];
    int per = nbins >> 8;
    unsigned s = 0;
    int base = threadIdx.x * per;
    for (int j = 0; j < per; j++) s += g_h[base + j];
    tsum[threadIdx.x] = s;
    unsigned ws = s;
    ws += __shfl_xor_sync(0xFFFFFFFFu, ws, 16);
    ws += __shfl_xor_sync(0xFFFFFFFFu, ws, 8);
    ws += __shfl_xor_sync(0xFFFFFFFFu, ws, 4);
    ws += __shfl_xor_sync(0xFFFFFFFFu, ws, 2);
    ws += __shfl_xor_sync(0xFFFFFFFFu, ws, 1);
    if ((threadIdx.x & 31) == 0) wsum[threadIdx.x >> 5] = ws;
    __syncthreads();
    if (threadIdx.x == 0) {
        unsigned r = g_rank;
        int w = 7;
        for (; w > 0; w--) { if (r < wsum[w]) break; r -= wsum[w]; }
        int t = 31;
        for (; t > 0; t--) { unsigned c = tsum[w * 32 + t]; if (r < c) break; r -= c; }
        int b = (w * 32 + t) * per;
        int j = per - 1;
        for (; j > 0; j--) { unsigned c = g_h[b + j]; if (r < c) break; r -= c; }
        unsigned d = (unsigned)(b + j);
        unsigned p = (g_pref << append_bits) | d;
        g_pref = p;
        g_rank = r;
        if (final_stage) { g_key32 = p; g_thresh = finv_map(p); }
    }
    __syncthreads();
    for (int j = threadIdx.x; j < nbins; j += 256) g_h[j] = 0;
    __syncthreads();
}

// Grid barrier; last block selects digit and resets a previous phase's
// counter pair (safe: all blocks already passed that phase).
__device__ void resolve_sync(int ph, int reset_ph, int nbins,
                             int append_bits, int fin) {
    __threadfence();
    __syncthreads();
    __shared__ unsigned slast;
    if (threadIdx.x == 0)
        slast = (atomicAdd(&g_ctr[ph], 1u) == gridDim.x - 1u) ? 1u : 0u;
    __syncthreads();
    if (slast) {
        select_digitN(nbins, append_bits, fin);
        if (threadIdx.x == 0 && reset_ph >= 0) {
            g_ctr[reset_ph] = 0;
            g_go[reset_ph] = 0;
        }
        __threadfence();
        if (threadIdx.x == 0) *(volatile unsigned*)&g_go[ph] = 1u;
    } else {
        if (threadIdx.x == 0)
            while (*(volatile unsigned*)&g_go[ph] == 0u) __nanosleep(64);
        __syncthreads();
        __threadfence();
    }
    __syncthreads();
}

// ---------------------------------------------------------------------------
__global__ void __launch_bounds__(NT) k_pass1(
        const uint4* __restrict__ a0, int n0,
        const uint4* __restrict__ a1, int n1,
        const uint4* __restrict__ a2, int n2,
        uint4* __restrict__ out,
        const int* mf_ptr, int host_mf, long long ntot) {
    __shared__ unsigned shh[HBINS];
    for (int j = threadIdx.x; j < HBINS; j += NT) shh[j] = 0;
    __syncthreads();

    int tid = blockIdx.x * blockDim.x + threadIdx.x;
    int stride = gridDim.x * blockDim.x;
    unsigned lane = threadIdx.x & 31u;
    unsigned gw = (unsigned)tid >> 5;
    unsigned sbase = gw * SLICE;
    unsigned lt = (lane == 31u) ? 0x7FFFFFFFu : ((1u << lane) - 1u);
    unsigned wo = 0;
    bool ovf = false;

#define P1_BODY(ARR, N, OUTP, EO)                                             \
    for (int i = tid; ; i += stride) {                                        \
        bool valid = i < (N);                                                 \
        if (!__any_sync(0xFFFFFFFFu, valid)) break;                           \
        uint4 v = valid ? __ldcs(&(ARR)[i]) : make_uint4(0u, 0u, 0u, 0u);     \
        unsigned k0 = fmap_u(v.x), k1 = fmap_u(v.y);                          \
        unsigned k2 = fmap_u(v.z), k3 = fmap_u(v.w);                          \
        bool c0 = valid && k0 >= FKEY, c1 = valid && k1 >= FKEY;              \
        bool c2 = valid && k2 >= FKEY, c3 = valid && k3 >= FKEY;              \
        if (valid) {                                                          \
            uint4 w;                                                          \
            w.x = c0 ? v.x : 0u;  w.y = c1 ? v.y : 0u;                        \
            w.z = c2 ? v.z : 0u;  w.w = c3 ? v.w : 0u;                        \
            __stcs(&(OUTP)[i], w);                                            \
        }                                                                     \
        unsigned b0 = __ballot_sync(0xFFFFFFFFu, c0);                         \
        unsigned b1 = __ballot_sync(0xFFFFFFFFu, c1);                         \
        unsigned b2 = __ballot_sync(0xFFFFFFFFu, c2);                         \
        unsigned b3 = __ballot_sync(0xFFFFFFFFu, c3);                         \
        unsigned t0 = __popc(b0), t1 = __popc(b1);                            \
        unsigned t2 = __popc(b2), t3 = __popc(b3);                            \
        unsigned tot = t0 + t1 + t2 + t3;                                     \
        if (tot) {                                                            \
            if (wo + tot <= SLICE) {                                          \
                unsigned o = sbase + wo;                                      \
                unsigned ib = (EO) + 4u * (unsigned)i;                        \
                unsigned p;                                                   \
                if (c0) { p = o + __popc(b0 & lt);                            \
                          g_key[p] = k0; g_idx[p] = ib;                       \
                          atomicAdd(&shh[k0 >> 20], 1u); }                    \
                o += t0;                                                      \
                if (c1) { p = o + __popc(b1 & lt);                            \
                          g_key[p] = k1; g_idx[p] = ib + 1u;                  \
                          atomicAdd(&shh[k1 >> 20], 1u); }                    \
                o += t1;                                                      \
                if (c2) { p = o + __popc(b2 & lt);                            \
                          g_key[p] = k2; g_idx[p] = ib + 2u;                  \
                          atomicAdd(&shh[k2 >> 20], 1u); }                    \
                o += t2;                                                      \
                if (c3) { p = o + __popc(b3 & lt);                            \
                          g_key[p] = k3; g_idx[p] = ib + 3u;                  \
                          atomicAdd(&shh[k3 >> 20], 1u); }                    \
                wo += tot;                                                    \
            } else {                                                          \
                ovf = true;                                                   \
            }                                                                 \
        }                                                                     \
    }
    P1_BODY(a0, n0, out, 0u)
    P1_BODY(a1, n1, out + n0, 4u * (unsigned)n0)
    P1_BODY(a2, n2, out + n0 + n1, 4u * (unsigned)(n0 + n1))
#undef P1_BODY

    if (ovf) g_overflow = 1;
    if (lane == 0) {
        g_warpcnt[gw] = wo;
        atomicAdd(&g_nscratch, wo);
    }
    __syncthreads();
    for (int j = threadIdx.x; j < HBINS; j += NT)
        if (shh[j]) atomicAdd(&g_h[j], shh[j]);
    __threadfence();

    __shared__ unsigned islast;
    if (threadIdx.x == 0)
        islast = (atomicAdd(&g_ctr[0], 1u) == gridDim.x - 1u) ? 1u : 0u;
    __syncthreads();
    if (!islast) return;

    __shared__ int smode;
    if (threadIdx.x == 0) {
        long long mf = (mf_ptr != nullptr) ? (long long)(*mf_ptr)
                                           : (long long)host_mf;
        if (mf < 0) mf = 0;
        int mode;
        if (mf >= ntot)                                        mode = 2;
        else if (g_overflow || (long long)g_nscratch < mf + 1) mode = 1;
        else                                                   mode = 0;
        g_mode = mode;
        smode = mode;
        g_rank = (unsigned)mf;
        g_pref = 0;
        g_cand_cnt = 0;          // reset for resolve (used only there)
        if (mode == 2) g_thresh = 0.0f;
    }
    __syncthreads();
    if (smode == 0) {
        select_digitN(HBINS, 12, 0);
    } else {
        // clear candidate hist (stale counts) for fallback / trivial modes
        for (int j = threadIdx.x; j < HBINS; j += NT) g_h[j] = 0;
    }
}

// ---------------------------------------------------------------------------
// Persistent resolve kernel.
__global__ void __launch_bounds__(NT) k_resolve(
        const uint4* __restrict__ a0, int n0,
        const uint4* __restrict__ a1, int n1,
        const uint4* __restrict__ a2, int n2,
        float4* __restrict__ out) {
    __shared__ unsigned shh[HBINS];
    // Reset pass1-only state for the next graph replay (pass1 has completed).
    if (blockIdx.x == 0 && threadIdx.x == 0) {
        g_ctr[0] = 0; g_nscratch = 0; g_overflow = 0;
    }
    int mode = g_mode;
    unsigned lane = threadIdx.x & 31u;
    unsigned lt = (lane == 31u) ? 0x7FFFFFFFu : ((1u << lane) - 1u);
    unsigned w = (blockIdx.x * blockDim.x + threadIdx.x) >> 5;
    unsigned nw = (gridDim.x * blockDim.x) >> 5;
    int tid = blockIdx.x * blockDim.x + threadIdx.x;
    int stride = gridDim.x * blockDim.x;
    float* of = (float*)out;

    if (mode == 0) {
        // ---- Phase A: scan slices; zero below-prefix12; compact matches;
        //      hist bits[19:8] ----
        for (int j = threadIdx.x; j < HBINS; j += NT) shh[j] = 0;
        __syncthreads();
        {
            const unsigned pref12 = g_pref;
            for (unsigned s = w; s < NWARP; s += nw) {
                unsigned cnt = g_warpcnt[s];
                if (cnt > SLICE) cnt = SLICE;
                const unsigned* kp = &g_key[s * SLICE];
                const unsigned* ip = &g_idx[s * SLICE];
                for (unsigned j = 0; j < cnt; j += 32) {
                    unsigned i = j + lane;
                    bool valid = i < cnt;
                    unsigned k = valid ? kp[i] : 0u;
                    unsigned id = valid ? ip[i] : 0u;
                    unsigned p12 = k >> 20;
                    if (valid && p12 < pref12) of[id] = 0.0f;
                    bool match = valid && (p12 == pref12);
                    unsigned bm = __ballot_sync(0xFFFFFFFFu, match);
                    unsigned n = __popc(bm);
                    if (n) {
                        unsigned base = 0;
                        if (lane == 0) base = atomicAdd(&g_cand_cnt, n);
                        base = __shfl_sync(0xFFFFFFFFu, base, 0);
                        if (match) {
                            unsigned pos = base + __popc(bm & lt);
                            g_ck[pos] = k;
                            g_ci[pos] = id;
                            atomicAdd(&shh[(k >> 8) & 4095u], 1u);
                        }
                    }
                }
            }
        }
        __syncthreads();
        for (int j = threadIdx.x; j < HBINS; j += NT)
            if (shh[j]) atomicAdd(&g_h[j], shh[j]);
        resolve_sync(1, -1, 4096, 12, 0);

        // ---- Phase B: scan cbuf; zero below-prefix24; hist bits[7:0] ----
        for (int j = threadIdx.x; j < 256; j += NT) shh[j] = 0;
        __syncthreads();
        unsigned cc = *(volatile unsigned*)&g_cand_cnt;
        if (cc > CBUF_CAP) cc = CBUF_CAP;
        const unsigned pref24 = *(volatile unsigned*)&g_pref;
        for (unsigned i = tid; i < cc; i += (unsigned)stride) {
            unsigned k = g_ck[i];
            unsigned p24 = k >> 8;
            if (p24 < pref24) of[g_ci[i]] = 0.0f;
            else if (p24 == pref24) atomicAdd(&shh[k & 255u], 1u);
        }
        __syncthreads();
        for (int j = threadIdx.x; j < 256; j += NT)
            if (shh[j]) atomicAdd(&g_h[j], shh[j]);
        resolve_sync(2, 1, 256, 8, 1);

        // ---- Phase C: zero prefix24-matched entries below exact key ----
        const unsigned kf = *(volatile unsigned*)&g_key32;
        for (unsigned i = tid; i < cc; i += (unsigned)stride) {
            unsigned k = g_ck[i];
            if ((k >> 8) == pref24 && k < kf) of[g_ci[i]] = 0.0f;
        }
        // exit handshake: last finisher resets phase-2 + handshake counters
        __threadfence();
        __syncthreads();
        if (threadIdx.x == 0) {
            if (atomicAdd(&g_ctr[6], 1u) == gridDim.x - 1u) {
                g_ctr[2] = 0; g_go[2] = 0; g_ctr[6] = 0;
            }
        }
        return;
    }

    if (mode == 1) {
        // ---- Fallback: 3 full-read hist phases (12+12+8 bits) ----
#define FB_HIST(SDP, DMASK, PREF_SH)                                          \
        {                                                                     \
            const unsigned pref = *(volatile unsigned*)&g_pref;               \
            for (int i = tid; i < n0; i += stride) {                          \
                uint4 v = __ldcs(&a0[i]);                                     \
                unsigned kk[4] = {fmap_u(v.x), fmap_u(v.y),                   \
                                  fmap_u(v.z), fmap_u(v.w)};                  \
                for (int q = 0; q < 4; q++)                                   \
                    if ((PREF_SH) < 0 || (kk[q] >> (PREF_SH)) == pref)        \
                        atomicAdd(&shh[(kk[q] >> (SDP)) & (DMASK)], 1u);      \
            }                                                                 \
            for (int i = tid; i < n1; i += stride) {                          \
                uint4 v = __ldcs(&a1[i]);                                     \
                unsigned kk[4] = {fmap_u(v.x), fmap_u(v.y),                   \
                                  fmap_u(v.z), fmap_u(v.w)};                  \
                for (int q = 0; q < 4; q++)                                   \
                    if ((PREF_SH) < 0 || (kk[q] >> (PREF_SH)) == pref)        \
                        atomicAdd(&shh[(kk[q] >> (SDP)) & (DMASK)], 1u);      \
            }                                                                 \
            for (int i = tid; i < n2; i += stride) {                          \
                uint4 v = __ldcs(&a2[i]);                                     \
                unsigned kk[4] = {fmap_u(v.x), fmap_u(v.y),                   \
                                  fmap_u(v.z), fmap_u(v.w)};                  \
                for (int q = 0; q < 4; q++)                                   \
                    if ((PREF_SH) < 0 || (kk[q] >> (PREF_SH)) == pref)        \
                        atomicAdd(&shh[(kk[q] >> (SDP)) & (DMASK)], 1u);      \
            }                                                                 \
        }
        for (int j = threadIdx.x; j < HBINS; j += NT) shh[j] = 0;
        __syncthreads();
        FB_HIST(20, 4095u, -1)
        __syncthreads();
        for (int j = threadIdx.x; j < HBINS; j += NT)
            if (shh[j]) atomicAdd(&g_h[j], shh[j]);
        resolve_sync(3, -1, 4096, 12, 0);

        for (int j = threadIdx.x; j < HBINS; j += NT) shh[j] = 0;
        __syncthreads();
        FB_HIST(8, 4095u, 20)
        __syncthreads();
        for (int j = threadIdx.x; j < HBINS; j += NT)
            if (shh[j]) atomicAdd(&g_h[j], shh[j]);
        resolve_sync(4, 3, 4096, 12, 0);

        for (int j = threadIdx.x; j < 256; j += NT) shh[j] = 0;
        __syncthreads();
        FB_HIST(0, 255u, 8)
        __syncthreads();
        for (int j = threadIdx.x; j < 256; j += NT)
            if (shh[j]) atomicAdd(&g_h[j], shh[j]);
        resolve_sync(5, 4, 256, 8, 1);
#undef FB_HIST
    }

    // ---- Full rewrite (mode 1 after select, or mode 2 with thresh=0) ----
    {
        const float th = *(volatile float*)&g_thresh;
        const float4* f0 = (const float4*)a0;
        const float4* f1 = (const float4*)a1;
        const float4* f2 = (const float4*)a2;
        for (int i = tid; i < n0; i += stride) {
            float4 v = f0[i];
            v.x = (v.x < th) ? 0.0f : v.x;  v.y = (v.y < th) ? 0.0f : v.y;
            v.z = (v.z < th) ? 0.0f : v.z;  v.w = (v.w < th) ? 0.0f : v.w;
            out[i] = v;
        }
        float4* o1 = out + n0;
        for (int i = tid; i < n1; i += stride) {
            float4 v = f1[i];
            v.x = (v.x < th) ? 0.0f : v.x;  v.y = (v.y < th) ? 0.0f : v.y;
            v.z = (v.z < th) ? 0.0f : v.z;  v.w = (v.w < th) ? 0.0f : v.w;
            o1[i] = v;
        }
        float4* o2 = out + n0 + n1;
        for (int i = tid; i < n2; i += stride) {
            float4 v = f2[i];
            v.x = (v.x < th) ? 0.0f : v.x;  v.y = (v.y < th) ? 0.0f : v.y;
            v.z = (v.z < th) ? 0.0f : v.z;  v.w = (v.w < th) ? 0.0f : v.w;
            o2[i] = v;
        }
    }
    // cleanup for mode 1 (mode 2 touched no counters)
    if (mode == 1) {
        __threadfence();
        __syncthreads();
        if (threadIdx.x == 0) {
            if (atomicAdd(&g_ctr[7], 1u) == gridDim.x - 1u) {
                g_ctr[5] = 0; g_go[5] = 0; g_ctr[7] = 0;
            }
        }
    }
}

// ============================================================================
extern "C" void kernel_launch(void* const* d_in, const int* in_sizes, int n_in,
                              void* d_out, int out_size) {
    const float* e  = (const float*)d_in[0];
    const float* m  = (const float*)d_in[1];
    const float* dp = (const float*)d_in[2];
    const int* mf_ptr = (n_in >= 4) ? (const int*)d_in[3] : nullptr;
    int ne = in_sizes[0], nm = in_sizes[1], nd = in_sizes[2];
    long long ntot = (long long)ne + (long long)nm + (long long)nd;
    int ne4 = ne / 4, nm4 = nm / 4, nd4 = nd / 4;

    const uint4* u0 = (const uint4*)e;
    const uint4* u1 = (const uint4*)m;
    const uint4* u2 = (const uint4*)dp;

    k_pass1<<<NB, NT>>>(u0, ne4, u1, nm4, u2, nd4, (uint4*)d_out,
                        mf_ptr, 500000, ntot);
    k_resolve<<<RGRID, NT>>>(u0, ne4, u1, nm4, u2, nd4, (float4*)d_out);
}

// round 8
// speedup vs baseline: 1.1112x; 1.1112x over previous
#include <cuda_runtime.h>
#include <stdint.h>

// ============================================================================
// One-sweep speculative radix-select threshold kernel (v8).
//
// thresh = rank-mf (0-based) entry of the descending sort of all inputs.
// out[i] = x[i] < thresh ? 0 : x[i].
//
// Key map (order-preserving): key = u ^ (sign ? 0xFFFFFFFF : 0x80000000).
//
// THREE launches (no init kernel; device statics zero at load and every
// kernel's last block resets the previous kernel's state for graph replay):
//  pass1:  read all, write out thresholded at 1.9375, compact candidate
//          key/idx into per-warp slices, smem 4096-bin hist of key>>20.
//          Last block decides mode + selects digit1 (12 bits).
//  round2: scan slices; zero out[] below 12-bit prefix; compact prefix-
//          matched (k,idx) densely into g_ck/g_ci; smem hist bits[19:8].
//          Last block selects digit2 (-> 24-bit prefix).
//  tail:   scan dense buffer; zero below 24-bit prefix; collect matched
//          stragglers + 256-bin hist of bits[7:0]. Last block selects the
//          final digit -> exact key, zeroes stragglers below it.
//          Fallback (mode 1): full-read hist phases + rewrite, gated.
//          Trivial (mode 2): thresh=0 rewrite.
// ============================================================================

#define NB     1024
#define NT     256
#define NWARP  (NB * NT / 32)     // 8192
#define SLICE  256u
#define CBUF_CAP (NWARP * SLICE)  // 2M entries
#define MCAP   16384u
#define FKEY   0xBFF80000u        // key(+1.9375f)
#define HBINS  4096
#define TGRID  64

__device__ unsigned g_h[HBINS];
__device__ unsigned g_key[NWARP * SLICE];   // 8 MB
__device__ unsigned g_idx[NWARP * SLICE];   // 8 MB
__device__ unsigned g_ck[CBUF_CAP];         // 8 MB dense in-bin keys
__device__ unsigned g_ci[CBUF_CAP];         // 8 MB dense in-bin idx
__device__ unsigned g_mk[MCAP];             // straggler keys
__device__ unsigned g_mi[MCAP];             // straggler idx
__device__ unsigned g_warpcnt[NWARP];
__device__ unsigned g_ctr[8];
__device__ unsigned g_go[8];
__device__ unsigned g_cand_cnt;
__device__ unsigned g_mcnt;
__device__ unsigned g_nscratch;
__device__ int      g_mode;       // 0=spec, 1=fallback, 2=trivial
__device__ int      g_overflow;
__device__ unsigned g_pref;       // accumulated digit prefix (right-aligned)
__device__ unsigned g_rank;       // residual rank
__device__ unsigned g_key32;      // final exact key
__device__ float    g_thresh;

__device__ __forceinline__ unsigned fmap_u(unsigned u) {
    return u ^ ((unsigned)((int)u >> 31) | 0x80000000u);
}
__device__ __forceinline__ float finv_map(unsigned k) {
    unsigned u = (k & 0x80000000u) ? (k ^ 0x80000000u) : ~k;
    return __uint_as_float(u);
}

// Block-cooperative descending rank-select over g_h[0..nbins). 256 threads.
// Appends digit to g_pref, updates g_rank, zeroes g_h[0..nbins).
__device__ void select_digitN(int nbins, int append_bits, int final_stage) {
    __shared__ unsigned tsum[256];
    __shared__ unsigned wsum[8];
    int per = nbins >> 8;
    unsigned s = 0;
    int base = threadIdx.x * per;
    for (int j = 0; j < per; j++) s += g_h[base + j];
    tsum[threadIdx.x] = s;
    unsigned ws = s;
    ws += __shfl_xor_sync(0xFFFFFFFFu, ws, 16);
    ws += __shfl_xor_sync(0xFFFFFFFFu, ws, 8);
    ws += __shfl_xor_sync(0xFFFFFFFFu, ws, 4);
    ws += __shfl_xor_sync(0xFFFFFFFFu, ws, 2);
    ws += __shfl_xor_sync(0xFFFFFFFFu, ws, 1);
    if ((threadIdx.x & 31) == 0) wsum[threadIdx.x >> 5] = ws;
    __syncthreads();
    if (threadIdx.x == 0) {
        unsigned r = g_rank;
        int w = 7;
        for (; w > 0; w--) { if (r < wsum[w]) break; r -= wsum[w]; }
        int t = 31;
        for (; t > 0; t--) { unsigned c = tsum[w * 32 + t]; if (r < c) break; r -= c; }
        int b = (w * 32 + t) * per;
        int j = per - 1;
        for (; j > 0; j--) { unsigned c = g_h[b + j]; if (r < c) break; r -= c; }
        unsigned d = (unsigned)(b + j);
        unsigned p = (g_pref << append_bits) | d;
        g_pref = p;
        g_rank = r;
        if (final_stage) { g_key32 = p; g_thresh = finv_map(p); }
    }
    __syncthreads();
    for (int j = threadIdx.x; j < nbins; j += 256) g_h[j] = 0;
    __syncthreads();
}

// Spin barrier used ONLY by the fallback path (mode 1).
__device__ void fb_sync(int ph, int nbins, int append_bits, int fin) {
    __threadfence();
    __syncthreads();
    __shared__ unsigned slast;
    if (threadIdx.x == 0)
        slast = (atomicAdd(&g_ctr[ph], 1u) == gridDim.x - 1u) ? 1u : 0u;
    __syncthreads();
    if (slast) {
        select_digitN(nbins, append_bits, fin);
        __threadfence();
        if (threadIdx.x == 0) *(volatile unsigned*)&g_go[ph] = 1u;
    } else {
        if (threadIdx.x == 0)
            while (*(volatile unsigned*)&g_go[ph] == 0u) __nanosleep(64);
        __syncthreads();
        __threadfence();
    }
    __syncthreads();
}

// ---------------------------------------------------------------------------
__global__ void __launch_bounds__(NT) k_pass1(
        const uint4* __restrict__ a0, int n0,
        const uint4* __restrict__ a1, int n1,
        const uint4* __restrict__ a2, int n2,
        uint4* __restrict__ out,
        const int* mf_ptr, int host_mf, long long ntot) {
    __shared__ unsigned shh[HBINS];
    for (int j = threadIdx.x; j < HBINS; j += NT) shh[j] = 0;
    __syncthreads();

    int tid = blockIdx.x * blockDim.x + threadIdx.x;
    int stride = gridDim.x * blockDim.x;
    unsigned lane = threadIdx.x & 31u;
    unsigned gw = (unsigned)tid >> 5;
    unsigned sbase = gw * SLICE;
    unsigned lt = (lane == 31u) ? 0x7FFFFFFFu : ((1u << lane) - 1u);
    unsigned wo = 0;
    bool ovf = false;

#define P1_BODY(ARR, N, OUTP, EO)                                             \
    for (int i = tid; ; i += stride) {                                        \
        bool valid = i < (N);                                                 \
        if (!__any_sync(0xFFFFFFFFu, valid)) break;                           \
        uint4 v = valid ? __ldcs(&(ARR)[i]) : make_uint4(0u, 0u, 0u, 0u);     \
        unsigned k0 = fmap_u(v.x), k1 = fmap_u(v.y);                          \
        unsigned k2 = fmap_u(v.z), k3 = fmap_u(v.w);                          \
        bool c0 = valid && k0 >= FKEY, c1 = valid && k1 >= FKEY;              \
        bool c2 = valid && k2 >= FKEY, c3 = valid && k3 >= FKEY;              \
        if (valid) {                                                          \
            uint4 w;                                                          \
            w.x = c0 ? v.x : 0u;  w.y = c1 ? v.y : 0u;                        \
            w.z = c2 ? v.z : 0u;  w.w = c3 ? v.w : 0u;                        \
            __stcs(&(OUTP)[i], w);                                            \
        }                                                                     \
        unsigned b0 = __ballot_sync(0xFFFFFFFFu, c0);                         \
        unsigned b1 = __ballot_sync(0xFFFFFFFFu, c1);                         \
        unsigned b2 = __ballot_sync(0xFFFFFFFFu, c2);                         \
        unsigned b3 = __ballot_sync(0xFFFFFFFFu, c3);                         \
        unsigned t0 = __popc(b0), t1 = __popc(b1);                            \
        unsigned t2 = __popc(b2), t3 = __popc(b3);                            \
        unsigned tot = t0 + t1 + t2 + t3;                                     \
        if (tot) {                                                            \
            if (wo + tot <= SLICE) {                                          \
                unsigned o = sbase + wo;                                      \
                unsigned ib = (EO) + 4u * (unsigned)i;                        \
                unsigned p;                                                   \
                if (c0) { p = o + __popc(b0 & lt);                            \
                          g_key[p] = k0; g_idx[p] = ib;                       \
                          atomicAdd(&shh[k0 >> 20], 1u); }                    \
                o += t0;                                                      \
                if (c1) { p = o + __popc(b1 & lt);                            \
                          g_key[p] = k1; g_idx[p] = ib + 1u;                  \
                          atomicAdd(&shh[k1 >> 20], 1u); }                    \
                o += t1;                                                      \
                if (c2) { p = o + __popc(b2 & lt);                            \
                          g_key[p] = k2; g_idx[p] = ib + 2u;                  \
                          atomicAdd(&shh[k2 >> 20], 1u); }                    \
                o += t2;                                                      \
                if (c3) { p = o + __popc(b3 & lt);                            \
                          g_key[p] = k3; g_idx[p] = ib + 3u;                  \
                          atomicAdd(&shh[k3 >> 20], 1u); }                    \
                wo += tot;                                                    \
            } else {                                                          \
                ovf = true;                                                   \
            }                                                                 \
        }                                                                     \
    }
    P1_BODY(a0, n0, out, 0u)
    P1_BODY(a1, n1, out + n0, 4u * (unsigned)n0)
    P1_BODY(a2, n2, out + n0 + n1, 4u * (unsigned)(n0 + n1))
#undef P1_BODY

    if (ovf) g_overflow = 1;
    if (lane == 0) {
        g_warpcnt[gw] = wo;
        atomicAdd(&g_nscratch, wo);
    }
    __syncthreads();
    for (int j = threadIdx.x; j < HBINS; j += NT)
        if (shh[j]) atomicAdd(&g_h[j], shh[j]);
    __threadfence();

    __shared__ unsigned islast;
    if (threadIdx.x == 0)
        islast = (atomicAdd(&g_ctr[0], 1u) == gridDim.x - 1u) ? 1u : 0u;
    __syncthreads();
    if (!islast) return;

    __shared__ int smode;
    if (threadIdx.x == 0) {
        long long mf = (mf_ptr != nullptr) ? (long long)(*mf_ptr)
                                           : (long long)host_mf;
        if (mf < 0) mf = 0;
        int mode;
        if (mf >= ntot)                                        mode = 2;
        else if (g_overflow || (long long)g_nscratch < mf + 1) mode = 1;
        else                                                   mode = 0;
        g_mode = mode;
        smode = mode;
        g_rank = (unsigned)mf;
        g_pref = 0;
        if (mode == 2) g_thresh = 0.0f;
    }
    __syncthreads();
    if (smode == 0) {
        select_digitN(HBINS, 12, 0);
    } else {
        // clear stale candidate hist for fallback / trivial modes
        for (int j = threadIdx.x; j < HBINS; j += NT) g_h[j] = 0;
    }
}

// ---------------------------------------------------------------------------
// round2: warp w handles slice w (grid*blockDim/32 == NWARP exactly).
__global__ void __launch_bounds__(NT) k_round2(float4* __restrict__ out) {
    __shared__ unsigned shh[HBINS];
    int mode = g_mode;
    if (mode == 0) {
        for (int j = threadIdx.x; j < HBINS; j += NT) shh[j] = 0;
        __syncthreads();

        unsigned lane = threadIdx.x & 31u;
        unsigned lt = (lane == 31u) ? 0x7FFFFFFFu : ((1u << lane) - 1u);
        unsigned w = (blockIdx.x * blockDim.x + threadIdx.x) >> 5;
        const unsigned pref12 = g_pref;
        float* of = (float*)out;

        unsigned cnt = g_warpcnt[w];
        if (cnt > SLICE) cnt = SLICE;
        const unsigned* kp = &g_key[w * SLICE];
        const unsigned* ip = &g_idx[w * SLICE];
        for (unsigned j = 0; j < cnt; j += 32) {
            unsigned i = j + lane;
            bool valid = i < cnt;
            unsigned k = valid ? kp[i] : 0u;
            unsigned id = valid ? ip[i] : 0u;
            unsigned p12 = k >> 20;
            if (valid && p12 < pref12) of[id] = 0.0f;
            bool match = valid && (p12 == pref12);
            unsigned bm = __ballot_sync(0xFFFFFFFFu, match);
            unsigned n = __popc(bm);
            if (n) {
                unsigned base = 0;
                if (lane == 0) base = atomicAdd(&g_cand_cnt, n);
                base = __shfl_sync(0xFFFFFFFFu, base, 0);
                if (match) {
                    unsigned pos = base + __popc(bm & lt);
                    if (pos < CBUF_CAP) {
                        g_ck[pos] = k;
                        g_ci[pos] = id;
                    }
                    atomicAdd(&shh[(k >> 8) & 4095u], 1u);
                }
            }
        }
        __syncthreads();
        for (int j = threadIdx.x; j < HBINS; j += NT)
            if (shh[j]) atomicAdd(&g_h[j], shh[j]);
    }
    __threadfence();
    __shared__ unsigned islast;
    if (threadIdx.x == 0)
        islast = (atomicAdd(&g_ctr[1], 1u) == gridDim.x - 1u) ? 1u : 0u;
    __syncthreads();
    if (!islast) return;

    // last block: reset pass1 state for next replay
    if (threadIdx.x == 0) {
        g_ctr[0] = 0; g_nscratch = 0; g_overflow = 0;
    }
    if (mode == 0) select_digitN(HBINS, 12, 0);   // -> 24-bit prefix
}

// ---------------------------------------------------------------------------
__global__ void __launch_bounds__(NT) k_tail(
        const uint4* __restrict__ a0, int n0,
        const uint4* __restrict__ a1, int n1,
        const uint4* __restrict__ a2, int n2,
        float4* __restrict__ out) {
    __shared__ unsigned shh[HBINS];
    int mode = g_mode;
    int tid = blockIdx.x * blockDim.x + threadIdx.x;
    int stride = gridDim.x * blockDim.x;
    float* of = (float*)out;

    if (mode == 0) {
        for (int j = threadIdx.x; j < 256; j += NT) shh[j] = 0;
        __syncthreads();
        unsigned cc = g_cand_cnt;
        if (cc > CBUF_CAP) cc = CBUF_CAP;
        const unsigned pref24 = g_pref;
        for (unsigned i = tid; i < cc; i += (unsigned)stride) {
            unsigned k = g_ck[i];
            unsigned p24 = k >> 8;
            if (p24 < pref24) {
                of[g_ci[i]] = 0.0f;
            } else if (p24 == pref24) {
                unsigned pos = atomicAdd(&g_mcnt, 1u);
                if (pos < MCAP) { g_mk[pos] = k; g_mi[pos] = g_ci[i]; }
                atomicAdd(&shh[k & 255u], 1u);
            }
        }
        __syncthreads();
        for (int j = threadIdx.x; j < 256; j += NT)
            if (shh[j]) atomicAdd(&g_h[j], shh[j]);
        __threadfence();
        __shared__ unsigned islast;
        if (threadIdx.x == 0)
            islast = (atomicAdd(&g_ctr[2], 1u) == gridDim.x - 1u) ? 1u : 0u;
        __syncthreads();
        if (!islast) return;

        select_digitN(256, 8, 1);              // final: g_key32, g_thresh
        unsigned kf = g_key32;
        unsigned mc = g_mcnt;
        if (mc <= MCAP) {
            for (unsigned i = threadIdx.x; i < mc; i += NT)
                if (g_mk[i] < kf) of[g_mi[i]] = 0.0f;
        } else {
            // straggler list overflowed: rescan dense buffer (correctness path)
            for (unsigned i = threadIdx.x; i < cc; i += NT) {
                unsigned k = g_ck[i];
                if ((k >> 8) == pref24 && k < kf) of[g_ci[i]] = 0.0f;
            }
        }
        __syncthreads();
        if (threadIdx.x == 0) {
            g_cand_cnt = 0; g_mcnt = 0; g_ctr[1] = 0; g_ctr[2] = 0;
        }
        return;
    }

    if (mode == 1) {
        // ---- Fallback: 3 full-read hist phases (12+12+8 bits), spins ----
#define FB_HIST(SDP, DMASK, PREF_SH)                                          \
        {                                                                     \
            const unsigned pref = *(volatile unsigned*)&g_pref;               \
            for (int i = tid; i < n0; i += stride) {                          \
                uint4 v = __ldcs(&a0[i]);                                     \
                unsigned kk[4] = {fmap_u(v.x), fmap_u(v.y),                   \
                                  fmap_u(v.z), fmap_u(v.w)};                  \
                for (int q = 0; q < 4; q++)                                   \
                    if ((PREF_SH) < 0 || (kk[q] >> (PREF_SH)) == pref)        \
                        atomicAdd(&shh[(kk[q] >> (SDP)) & (DMASK)], 1u);      \
            }                                                                 \
            for (int i = tid; i < n1; i += stride) {                          \
                uint4 v = __ldcs(&a1[i]);                                     \
                unsigned kk[4] = {fmap_u(v.x), fmap_u(v.y),                   \
                                  fmap_u(v.z), fmap_u(v.w)};                  \
                for (int q = 0; q < 4; q++)                                   \
                    if ((PREF_SH) < 0 || (kk[q] >> (PREF_SH)) == pref)        \
                        atomicAdd(&shh[(kk[q] >> (SDP)) & (DMASK)], 1u);      \
            }                                                                 \
            for (int i = tid; i < n2; i += stride) {                          \
                uint4 v = __ldcs(&a2[i]);                                     \
                unsigned kk[4] = {fmap_u(v.x), fmap_u(v.y),                   \
                                  fmap_u(v.z), fmap_u(v.w)};                  \
                for (int q = 0; q < 4; q++)                                   \
                    if ((PREF_SH) < 0 || (kk[q] >> (PREF_SH)) == pref)        \
                        atomicAdd(&shh[(kk[q] >> (SDP)) & (DMASK)], 1u);      \
            }                                                                 \
        }
        for (int j = threadIdx.x; j < HBINS; j += NT) shh[j] = 0;
        __syncthreads();
        FB_HIST(20, 4095u, -1)
        __syncthreads();
        for (int j = threadIdx.x; j < HBINS; j += NT)
            if (shh[j]) atomicAdd(&g_h[j], shh[j]);
        fb_sync(3, 4096, 12, 0);

        for (int j = threadIdx.x; j < HBINS; j += NT) shh[j] = 0;
        __syncthreads();
        FB_HIST(8, 4095u, 20)
        __syncthreads();
        for (int j = threadIdx.x; j < HBINS; j += NT)
            if (shh[j]) atomicAdd(&g_h[j], shh[j]);
        fb_sync(4, 4096, 12, 0);

        for (int j = threadIdx.x; j < 256; j += NT) shh[j] = 0;
        __syncthreads();
        FB_HIST(0, 255u, 8)
        __syncthreads();
        for (int j = threadIdx.x; j < 256; j += NT)
            if (shh[j]) atomicAdd(&g_h[j], shh[j]);
        fb_sync(5, 256, 8, 1);
#undef FB_HIST
    }

    // ---- Full rewrite (mode 1 after select, or mode 2 with thresh=0) ----
    {
        const float th = *(volatile float*)&g_thresh;
        const float4* f0 = (const float4*)a0;
        const float4* f1 = (const float4*)a1;
        const float4* f2 = (const float4*)a2;
        for (int i = tid; i < n0; i += stride) {
            float4 v = f0[i];
            v.x = (v.x < th) ? 0.0f : v.x;  v.y = (v.y < th) ? 0.0f : v.y;
            v.z = (v.z < th) ? 0.0f : v.z;  v.w = (v.w < th) ? 0.0f : v.w;
            out[i] = v;
        }
        float4* o1 = out + n0;
        for (int i = tid; i < n1; i += stride) {
            float4 v = f1[i];
            v.x = (v.x < th) ? 0.0f : v.x;  v.y = (v.y < th) ? 0.0f : v.y;
            v.z = (v.z < th) ? 0.0f : v.z;  v.w = (v.w < th) ? 0.0f : v.w;
            o1[i] = v;
        }
        float4* o2 = out + n0 + n1;
        for (int i = tid; i < n2; i += stride) {
            float4 v = f2[i];
            v.x = (v.x < th) ? 0.0f : v.x;  v.y = (v.y < th) ? 0.0f : v.y;
            v.z = (v.z < th) ? 0.0f : v.z;  v.w = (v.w < th) ? 0.0f : v.w;
            o2[i] = v;
        }
    }
    // epilogue elect: reset counters for next replay
    __threadfence();
    __syncthreads();
    if (threadIdx.x == 0) {
        if (atomicAdd(&g_ctr[2], 1u) == gridDim.x - 1u) {
            g_ctr[1] = 0; g_ctr[2] = 0;
            g_cand_cnt = 0; g_mcnt = 0;
            g_ctr[3] = 0; g_ctr[4] = 0; g_ctr[5] = 0;
            g_go[3] = 0; g_go[4] = 0; g_go[5] = 0;
        }
    }
}

// ============================================================================
extern "C" void kernel_launch(void* const* d_in, const int* in_sizes, int n_in,
                              void* d_out, int out_size) {
    const float* e  = (const float*)d_in[0];
    const float* m  = (const float*)d_in[1];
    const float* dp = (const float*)d_in[2];
    const int* mf_ptr = (n_in >= 4) ? (const int*)d_in[3] : nullptr;
    int ne = in_sizes[0], nm = in_sizes[1], nd = in_sizes[2];
    long long ntot = (long long)ne + (long long)nm + (long long)nd;
    int ne4 = ne / 4, nm4 = nm / 4, nd4 = nd / 4;

    const uint4* u0 = (const uint4*)e;
    const uint4* u1 = (const uint4*)m;
    const uint4* u2 = (const uint4*)dp;

    k_pass1<<<NB, NT>>>(u0, ne4, u1, nm4, u2, nd4, (uint4*)d_out,
                        mf_ptr, 500000, ntot);
    k_round2<<<NB, NT>>>((float4*)d_out);
    k_tail<<<TGRID, NT>>>(u0, ne4, u1, nm4, u2, nd4, (float4*)d_out);
}

// round 9
// speedup vs baseline: 1.2397x; 1.1156x over previous
#include <cuda_runtime.h>
#include <stdint.h>

// ============================================================================
// One-sweep speculative radix-select threshold kernel (v9).
//
// thresh = rank-mf (0-based) entry of the descending sort of all inputs.
// out[i] = x[i] < thresh ? 0 : x[i].
//
// Key map (order-preserving): key = u ^ (sign ? 0xFFFFFFFF : 0x80000000).
//
// THREE launches (no init kernel; device statics zero at load and every
// kernel's last block resets the previous kernel's state for graph replay):
//  pass1:  read all, write out thresholded at 1.9375 (float compare, key
//          computed only for candidates), compact candidate key/idx into
//          per-warp slices, smem 4096-bin hist of key>>20.
//          Last block decides mode + selects digit1 (12 bits).
//  round2: scan slices; zero out[] below 12-bit prefix; block-aggregated
//          dense compaction of prefix-matched (k,idx); smem hist bits[19:8].
//          Last block selects digit2 (-> 24-bit prefix).
//  tail:   scan dense buffer; zero below 24-bit prefix; collect matched
//          stragglers + 256-bin hist of bits[7:0]. Last block selects the
//          final digit -> exact key, zeroes stragglers below it.
//          Fallback (mode 1): full-read hist phases + rewrite, gated.
//          Trivial (mode 2): thresh=0 rewrite.
// ============================================================================

#define NB     1024
#define NT     256
#define NWARP  (NB * NT / 32)     // 8192
#define SLICE  256u
#define CBUF_CAP (NWARP * SLICE)  // 2M entries
#define MCAP   16384u
#define FTH    1.9375f
#define HBINS  4096
#define TGRID  64

__device__ unsigned g_h[HBINS];
__device__ unsigned g_key[NWARP * SLICE];   // 8 MB
__device__ unsigned g_idx[NWARP * SLICE];   // 8 MB
__device__ unsigned g_ck[CBUF_CAP];         // 8 MB dense in-bin keys
__device__ unsigned g_ci[CBUF_CAP];         // 8 MB dense in-bin idx
__device__ unsigned g_mk[MCAP];             // straggler keys
__device__ unsigned g_mi[MCAP];             // straggler idx
__device__ unsigned g_warpcnt[NWARP];
__device__ unsigned g_ctr[8];
__device__ unsigned g_go[8];
__device__ unsigned g_cand_cnt;
__device__ unsigned g_mcnt;
__device__ unsigned g_nscratch;
__device__ int      g_mode;       // 0=spec, 1=fallback, 2=trivial
__device__ int      g_overflow;
__device__ unsigned g_pref;       // accumulated digit prefix (right-aligned)
__device__ unsigned g_rank;       // residual rank
__device__ unsigned g_key32;      // final exact key
__device__ float    g_thresh;

__device__ __forceinline__ unsigned fmap_u(unsigned u) {
    return u ^ ((unsigned)((int)u >> 31) | 0x80000000u);
}
__device__ __forceinline__ float finv_map(unsigned k) {
    unsigned u = (k & 0x80000000u) ? (k ^ 0x80000000u) : ~k;
    return __uint_as_float(u);
}

// Block-cooperative descending rank-select over g_h[0..nbins). 256 threads.
__device__ void select_digitN(int nbins, int append_bits, int final_stage) {
    __shared__ unsigned tsum[256];
    __shared__ unsigned wsum[8];
    int per = nbins >> 8;
    unsigned s = 0;
    int base = threadIdx.x * per;
    for (int j = 0; j < per; j++) s += g_h[base + j];
    tsum[threadIdx.x] = s;
    unsigned ws = s;
    ws += __shfl_xor_sync(0xFFFFFFFFu, ws, 16);
    ws += __shfl_xor_sync(0xFFFFFFFFu, ws, 8);
    ws += __shfl_xor_sync(0xFFFFFFFFu, ws, 4);
    ws += __shfl_xor_sync(0xFFFFFFFFu, ws, 2);
    ws += __shfl_xor_sync(0xFFFFFFFFu, ws, 1);
    if ((threadIdx.x & 31) == 0) wsum[threadIdx.x >> 5] = ws;
    __syncthreads();
    if (threadIdx.x == 0) {
        unsigned r = g_rank;
        int w = 7;
        for (; w > 0; w--) { if (r < wsum[w]) break; r -= wsum[w]; }
        int t = 31;
        for (; t > 0; t--) { unsigned c = tsum[w * 32 + t]; if (r < c) break; r -= c; }
        int b = (w * 32 + t) * per;
        int j = per - 1;
        for (; j > 0; j--) { unsigned c = g_h[b + j]; if (r < c) break; r -= c; }
        unsigned d = (unsigned)(b + j);
        unsigned p = (g_pref << append_bits) | d;
        g_pref = p;
        g_rank = r;
        if (final_stage) { g_key32 = p; g_thresh = finv_map(p); }
    }
    __syncthreads();
    for (int j = threadIdx.x; j < nbins; j += 256) g_h[j] = 0;
    __syncthreads();
}

// Spin barrier used ONLY by the fallback path (mode 1).
__device__ void fb_sync(int ph, int nbins, int append_bits, int fin) {
    __threadfence();
    __syncthreads();
    __shared__ unsigned slast;
    if (threadIdx.x == 0)
        slast = (atomicAdd(&g_ctr[ph], 1u) == gridDim.x - 1u) ? 1u : 0u;
    __syncthreads();
    if (slast) {
        select_digitN(nbins, append_bits, fin);
        __threadfence();
        if (threadIdx.x == 0) *(volatile unsigned*)&g_go[ph] = 1u;
    } else {
        if (threadIdx.x == 0)
            while (*(volatile unsigned*)&g_go[ph] == 0u) __nanosleep(64);
        __syncthreads();
        __threadfence();
    }
    __syncthreads();
}

// ---------------------------------------------------------------------------
__global__ void __launch_bounds__(NT) k_pass1(
        const uint4* __restrict__ a0, int n0,
        const uint4* __restrict__ a1, int n1,
        const uint4* __restrict__ a2, int n2,
        uint4* __restrict__ out,
        const int* mf_ptr, int host_mf, long long ntot) {
    __shared__ unsigned shh[HBINS];
    for (int j = threadIdx.x; j < HBINS; j += NT) shh[j] = 0;
    __syncthreads();

    int tid = blockIdx.x * blockDim.x + threadIdx.x;
    int stride = gridDim.x * blockDim.x;
    unsigned lane = threadIdx.x & 31u;
    unsigned gw = (unsigned)tid >> 5;
    unsigned sbase = gw * SLICE;
    unsigned lt = (lane == 31u) ? 0x7FFFFFFFu : ((1u << lane) - 1u);
    unsigned wo = 0;
    bool ovf = false;

#define P1_BODY(ARR, N, OUTP, EO)                                             \
    for (int i = tid; ; i += stride) {                                        \
        bool valid = i < (N);                                                 \
        if (!__any_sync(0xFFFFFFFFu, valid)) break;                           \
        uint4 v = valid ? __ldcs(&(ARR)[i]) : make_uint4(0u, 0u, 0u, 0u);     \
        /* candidate test: !(x < 1.9375f) matches reference's (x < thresh) */ \
        bool c0 = valid && !(__uint_as_float(v.x) < FTH);                     \
        bool c1 = valid && !(__uint_as_float(v.y) < FTH);                     \
        bool c2 = valid && !(__uint_as_float(v.z) < FTH);                     \
        bool c3 = valid && !(__uint_as_float(v.w) < FTH);                     \
        if (valid) {                                                          \
            uint4 w;                                                          \
            w.x = c0 ? v.x : 0u;  w.y = c1 ? v.y : 0u;                        \
            w.z = c2 ? v.z : 0u;  w.w = c3 ? v.w : 0u;                        \
            __stcs(&(OUTP)[i], w);                                            \
        }                                                                     \
        unsigned b0 = __ballot_sync(0xFFFFFFFFu, c0);                         \
        unsigned b1 = __ballot_sync(0xFFFFFFFFu, c1);                         \
        unsigned b2 = __ballot_sync(0xFFFFFFFFu, c2);                         \
        unsigned b3 = __ballot_sync(0xFFFFFFFFu, c3);                         \
        unsigned tot = __popc(b0) + __popc(b1) + __popc(b2) + __popc(b3);     \
        if (tot) {                                                            \
            if (wo + tot <= SLICE) {                                          \
                unsigned o = sbase + wo;                                      \
                unsigned ib = (EO) + 4u * (unsigned)i;                        \
                unsigned p;                                                   \
                if (c0) { unsigned k = fmap_u(v.x);                           \
                          p = o + __popc(b0 & lt);                            \
                          g_key[p] = k; g_idx[p] = ib;                        \
                          atomicAdd(&shh[k >> 20], 1u); }                     \
                o += __popc(b0);                                              \
                if (c1) { unsigned k = fmap_u(v.y);                           \
                          p = o + __popc(b1 & lt);                            \
                          g_key[p] = k; g_idx[p] = ib + 1u;                   \
                          atomicAdd(&shh[k >> 20], 1u); }                     \
                o += __popc(b1);                                              \
                if (c2) { unsigned k = fmap_u(v.z);                           \
                          p = o + __popc(b2 & lt);                            \
                          g_key[p] = k; g_idx[p] = ib + 2u;                   \
                          atomicAdd(&shh[k >> 20], 1u); }                     \
                o += __popc(b2);                                              \
                if (c3) { unsigned k = fmap_u(v.w);                           \
                          p = o + __popc(b3 & lt);                            \
                          g_key[p] = k; g_idx[p] = ib + 3u;                   \
                          atomicAdd(&shh[k >> 20], 1u); }                     \
                wo += tot;                                                    \
            } else {                                                          \
                ovf = true;                                                   \
            }                                                                 \
        }                                                                     \
    }
    P1_BODY(a0, n0, out, 0u)
    P1_BODY(a1, n1, out + n0, 4u * (unsigned)n0)
    P1_BODY(a2, n2, out + n0 + n1, 4u * (unsigned)(n0 + n1))
#undef P1_BODY

    if (ovf) g_overflow = 1;
    if (lane == 0) {
        g_warpcnt[gw] = wo;
        atomicAdd(&g_nscratch, wo);
    }
    __syncthreads();
    for (int j = threadIdx.x; j < HBINS; j += NT)
        if (shh[j]) atomicAdd(&g_h[j], shh[j]);
    __threadfence();

    __shared__ unsigned islast;
    if (threadIdx.x == 0)
        islast = (atomicAdd(&g_ctr[0], 1u) == gridDim.x - 1u) ? 1u : 0u;
    __syncthreads();
    if (!islast) return;

    __shared__ int smode;
    if (threadIdx.x == 0) {
        long long mf = (mf_ptr != nullptr) ? (long long)(*mf_ptr)
                                           : (long long)host_mf;
        if (mf < 0) mf = 0;
        int mode;
        if (mf >= ntot)                                        mode = 2;
        else if (g_overflow || (long long)g_nscratch < mf + 1) mode = 1;
        else                                                   mode = 0;
        g_mode = mode;
        smode = mode;
        g_rank = (unsigned)mf;
        g_pref = 0;
        if (mode == 2) g_thresh = 0.0f;
    }
    __syncthreads();
    if (smode == 0) {
        select_digitN(HBINS, 12, 0);
    } else {
        for (int j = threadIdx.x; j < HBINS; j += NT) g_h[j] = 0;
    }
}

// ---------------------------------------------------------------------------
// round2: warp w handles slice w (grid*blockDim/32 == NWARP exactly).
// Block-aggregated dense compaction: ONE global atomicAdd per block.
__global__ void __launch_bounds__(NT) k_round2(float4* __restrict__ out) {
    __shared__ unsigned shh[HBINS];
    __shared__ unsigned wcnt_s[NT / 32];
    __shared__ unsigned wbase_s[NT / 32];
    int mode = g_mode;
    if (mode == 0) {
        for (int j = threadIdx.x; j < HBINS; j += NT) shh[j] = 0;
        __syncthreads();

        unsigned lane = threadIdx.x & 31u;
        unsigned wip = threadIdx.x >> 5;
        unsigned lt = (lane == 31u) ? 0x7FFFFFFFu : ((1u << lane) - 1u);
        unsigned w = (blockIdx.x * blockDim.x + threadIdx.x) >> 5;
        const unsigned pref12 = g_pref;
        float* of = (float*)out;

        unsigned cnt = g_warpcnt[w];
        if (cnt > SLICE) cnt = SLICE;
        const unsigned* kp = &g_key[w * SLICE];
        const unsigned* ip = &g_idx[w * SLICE];

        // Pass A: zero below-prefix outputs, count matches.
        unsigned mcnt = 0;
        for (unsigned j = lane; j < cnt; j += 32) {
            unsigned k = kp[j];
            unsigned p12 = k >> 20;
            if (p12 < pref12) of[ip[j]] = 0.0f;
            mcnt += (p12 == pref12) ? 1u : 0u;
        }
        mcnt += __shfl_xor_sync(0xFFFFFFFFu, mcnt, 16);
        mcnt += __shfl_xor_sync(0xFFFFFFFFu, mcnt, 8);
        mcnt += __shfl_xor_sync(0xFFFFFFFFu, mcnt, 4);
        mcnt += __shfl_xor_sync(0xFFFFFFFFu, mcnt, 2);
        mcnt += __shfl_xor_sync(0xFFFFFFFFu, mcnt, 1);
        if (lane == 0) wcnt_s[wip] = mcnt;
        __syncthreads();
        if (threadIdx.x == 0) {
            unsigned tot = 0, b[NT / 32];
            for (int q = 0; q < NT / 32; q++) { b[q] = tot; tot += wcnt_s[q]; }
            unsigned base = tot ? atomicAdd(&g_cand_cnt, tot) : 0u;
            for (int q = 0; q < NT / 32; q++) wbase_s[q] = base + b[q];
        }
        __syncthreads();
        unsigned wb = wbase_s[wip];

        // Pass B: write matched entries densely (slice is L1-hot).
        for (unsigned j = 0; j < cnt; j += 32) {
            unsigned i = j + lane;
            bool valid = i < cnt;
            unsigned k = valid ? kp[i] : 0u;
            bool match = valid && ((k >> 20) == pref12);
            unsigned bm = __ballot_sync(0xFFFFFFFFu, match);
            if (match) {
                unsigned pos = wb + __popc(bm & lt);
                if (pos < CBUF_CAP) { g_ck[pos] = k; g_ci[pos] = ip[i]; }
                atomicAdd(&shh[(k >> 8) & 4095u], 1u);
            }
            wb += __popc(bm);
        }
        __syncthreads();
        for (int j = threadIdx.x; j < HBINS; j += NT)
            if (shh[j]) atomicAdd(&g_h[j], shh[j]);
    }
    __threadfence();
    __shared__ unsigned islast;
    if (threadIdx.x == 0)
        islast = (atomicAdd(&g_ctr[1], 1u) == gridDim.x - 1u) ? 1u : 0u;
    __syncthreads();
    if (!islast) return;

    if (threadIdx.x == 0) {
        g_ctr[0] = 0; g_nscratch = 0; g_overflow = 0;
    }
    if (mode == 0) select_digitN(HBINS, 12, 0);   // -> 24-bit prefix
}

// ---------------------------------------------------------------------------
__global__ void __launch_bounds__(NT) k_tail(
        const uint4* __restrict__ a0, int n0,
        const uint4* __restrict__ a1, int n1,
        const uint4* __restrict__ a2, int n2,
        float4* __restrict__ out) {
    __shared__ unsigned shh[HBINS];
    int mode = g_mode;
    int tid = blockIdx.x * blockDim.x + threadIdx.x;
    int stride = gridDim.x * blockDim.x;
    float* of = (float*)out;

    if (mode == 0) {
        for (int j = threadIdx.x; j < 256; j += NT) shh[j] = 0;
        __syncthreads();
        unsigned cc = g_cand_cnt;
        if (cc > CBUF_CAP) cc = CBUF_CAP;
        const unsigned pref24 = g_pref;
        for (unsigned i = tid; i < cc; i += (unsigned)stride) {
            unsigned k = g_ck[i];
            unsigned p24 = k >> 8;
            if (p24 < pref24) {
                of[g_ci[i]] = 0.0f;
            } else if (p24 == pref24) {
                unsigned pos = atomicAdd(&g_mcnt, 1u);
                if (pos < MCAP) { g_mk[pos] = k; g_mi[pos] = g_ci[i]; }
                atomicAdd(&shh[k & 255u], 1u);
            }
        }
        __syncthreads();
        for (int j = threadIdx.x; j < 256; j += NT)
            if (shh[j]) atomicAdd(&g_h[j], shh[j]);
        __threadfence();
        __shared__ unsigned islast;
        if (threadIdx.x == 0)
            islast = (atomicAdd(&g_ctr[2], 1u) == gridDim.x - 1u) ? 1u : 0u;
        __syncthreads();
        if (!islast) return;

        select_digitN(256, 8, 1);              // final: g_key32, g_thresh
        unsigned kf = g_key32;
        unsigned mc = g_mcnt;
        if (mc <= MCAP) {
            for (unsigned i = threadIdx.x; i < mc; i += NT)
                if (g_mk[i] < kf) of[g_mi[i]] = 0.0f;
        } else {
            for (unsigned i = threadIdx.x; i < cc; i += NT) {
                unsigned k = g_ck[i];
                if ((k >> 8) == pref24 && k < kf) of[g_ci[i]] = 0.0f;
            }
        }
        __syncthreads();
        if (threadIdx.x == 0) {
            g_cand_cnt = 0; g_mcnt = 0; g_ctr[1] = 0; g_ctr[2] = 0;
        }
        return;
    }

    if (mode == 1) {
        // ---- Fallback: 3 full-read hist phases (12+12+8 bits), spins ----
#define FB_HIST(SDP, DMASK, PREF_SH)                                          \
        {                                                                     \
            const unsigned pref = *(volatile unsigned*)&g_pref;               \
            for (int i = tid; i < n0; i += stride) {                          \
                uint4 v = __ldcs(&a0[i]);                                     \
                unsigned kk[4] = {fmap_u(v.x), fmap_u(v.y),                   \
                                  fmap_u(v.z), fmap_u(v.w)};                  \
                for (int q = 0; q < 4; q++)                                   \
                    if ((PREF_SH) < 0 || (kk[q] >> (PREF_SH)) == pref)        \
                        atomicAdd(&shh[(kk[q] >> (SDP)) & (DMASK)], 1u);      \
            }                                                                 \
            for (int i = tid; i < n1; i += stride) {                          \
                uint4 v = __ldcs(&a1[i]);                                     \
                unsigned kk[4] = {fmap_u(v.x), fmap_u(v.y),                   \
                                  fmap_u(v.z), fmap_u(v.w)};                  \
                for (int q = 0; q < 4; q++)                                   \
                    if ((PREF_SH) < 0 || (kk[q] >> (PREF_SH)) == pref)        \
                        atomicAdd(&shh[(kk[q] >> (SDP)) & (DMASK)], 1u);      \
            }                                                                 \
            for (int i = tid; i < n2; i += stride) {                          \
                uint4 v = __ldcs(&a2[i]);                                     \
                unsigned kk[4] = {fmap_u(v.x), fmap_u(v.y),                   \
                                  fmap_u(v.z), fmap_u(v.w)};                  \
                for (int q = 0; q < 4; q++)                                   \
                    if ((PREF_SH) < 0 || (kk[q] >> (PREF_SH)) == pref)        \
                        atomicAdd(&shh[(kk[q] >> (SDP)) & (DMASK)], 1u);      \
            }                                                                 \
        }
        for (int j = threadIdx.x; j < HBINS; j += NT) shh[j] = 0;
        __syncthreads();
        FB_HIST(20, 4095u, -1)
        __syncthreads();
        for (int j = threadIdx.x; j < HBINS; j += NT)
            if (shh[j]) atomicAdd(&g_h[j], shh[j]);
        fb_sync(3, 4096, 12, 0);

        for (int j = threadIdx.x; j < HBINS; j += NT) shh[j] = 0;
        __syncthreads();
        FB_HIST(8, 4095u, 20)
        __syncthreads();
        for (int j = threadIdx.x; j < HBINS; j += NT)
            if (shh[j]) atomicAdd(&g_h[j], shh[j]);
        fb_sync(4, 4096, 12, 0);

        for (int j = threadIdx.x; j < 256; j += NT) shh[j] = 0;
        __syncthreads();
        FB_HIST(0, 255u, 8)
        __syncthreads();
        for (int j = threadIdx.x; j < 256; j += NT)
            if (shh[j]) atomicAdd(&g_h[j], shh[j]);
        fb_sync(5, 256, 8, 1);
#undef FB_HIST
    }

    // ---- Full rewrite (mode 1 after select, or mode 2 with thresh=0) ----
    {
        const float th = *(volatile float*)&g_thresh;
        const float4* f0 = (const float4*)a0;
        const float4* f1 = (const float4*)a1;
        const float4* f2 = (const float4*)a2;
        for (int i = tid; i < n0; i += stride) {
            float4 v = f0[i];
            v.x = (v.x < th) ? 0.0f : v.x;  v.y = (v.y < th) ? 0.0f : v.y;
            v.z = (v.z < th) ? 0.0f : v.z;  v.w = (v.w < th) ? 0.0f : v.w;
            out[i] = v;
        }
        float4* o1 = out + n0;
        for (int i = tid; i < n1; i += stride) {
            float4 v = f1[i];
            v.x = (v.x < th) ? 0.0f : v.x;  v.y = (v.y < th) ? 0.0f : v.y;
            v.z = (v.z < th) ? 0.0f : v.z;  v.w = (v.w < th) ? 0.0f : v.w;
            o1[i] = v;
        }
        float4* o2 = out + n0 + n1;
        for (int i = tid; i < n2; i += stride) {
            float4 v = f2[i];
            v.x = (v.x < th) ? 0.0f : v.x;  v.y = (v.y < th) ? 0.0f : v.y;
            v.z = (v.z < th) ? 0.0f : v.z;  v.w = (v.w < th) ? 0.0f : v.w;
            o2[i] = v;
        }
    }
    __threadfence();
    __syncthreads();
    if (threadIdx.x == 0) {
        if (atomicAdd(&g_ctr[2], 1u) == gridDim.x - 1u) {
            g_ctr[1] = 0; g_ctr[2] = 0;
            g_cand_cnt = 0; g_mcnt = 0;
            g_ctr[3] = 0; g_ctr[4] = 0; g_ctr[5] = 0;
            g_go[3] = 0; g_go[4] = 0; g_go[5] = 0;
        }
    }
}

// ============================================================================
extern "C" void kernel_launch(void* const* d_in, const int* in_sizes, int n_in,
                              void* d_out, int out_size) {
    const float* e  = (const float*)d_in[0];
    const float* m  = (const float*)d_in[1];
    const float* dp = (const float*)d_in[2];
    const int* mf_ptr = (n_in >= 4) ? (const int*)d_in[3] : nullptr;
    int ne = in_sizes[0], nm = in_sizes[1], nd = in_sizes[2];
    long long ntot = (long long)ne + (long long)nm + (long long)nd;
    int ne4 = ne / 4, nm4 = nm / 4, nd4 = nd / 4;

    const uint4* u0 = (const uint4*)e;
    const uint4* u1 = (const uint4*)m;
    const uint4* u2 = (const uint4*)dp;

    k_pass1<<<NB, NT>>>(u0, ne4, u1, nm4, u2, nd4, (uint4*)d_out,
                        mf_ptr, 500000, ntot);
    k_round2<<<NB, NT>>>((float4*)d_out);
    k_tail<<<TGRID, NT>>>(u0, ne4, u1, nm4, u2, nd4, (float4*)d_out);
}